// round 1
// baseline (speedup 1.0000x reference)
#include <cuda_runtime.h>
#include <math.h>

#define D 128
#define BATCH 1024
#define MAXLEN 160
#define NMAX 114000
#define VMAX 50048

// ---------------- device scratch (no allocations allowed) ----------------
__device__ __align__(16) float g_csrc[D];
__device__ __align__(16) float g_cdst[D];
__device__ __align__(16) float g_ddot[512];
__device__ __align__(16) float g_pvs[VMAX];
__device__ __align__(16) float g_pvd[VMAX];
__device__ int   g_starts[BATCH];
__device__ __align__(16) float g_Wt[6 * D * D];        // transposed weights: q,k,v,o,f1,f2
__device__ __align__(16) float g_H  [(size_t)NMAX * D];
__device__ __align__(16) float g_Qn [(size_t)NMAX * D];
__device__ __align__(16) float g_q  [(size_t)NMAX * D];
__device__ __align__(16) float g_k  [(size_t)NMAX * D];
__device__ __align__(16) float g_v  [(size_t)NMAX * D];
__device__ __align__(16) float g_ctx[(size_t)NMAX * D];
__device__ __align__(16) float g_t1 [(size_t)NMAX * D];
__device__ __align__(16) float g_o2 [(size_t)NMAX * D];
__device__ __align__(16) float g_f1 [(size_t)NMAX * D];
__device__ __align__(16) float g_fin[(size_t)NMAX * D];

__device__ __forceinline__ float wsum(float v) {
#pragma unroll
    for (int o = 16; o; o >>= 1) v += __shfl_xor_sync(0xffffffffu, v, o);
    return v;
}

// ---------------- tiny precompute kernels ----------------
// c_src = a_src @ W,  c_dst = a_dst @ W   (contracts the att_W matmul away)
__global__ void k_cvec(const float* __restrict__ W, const float* __restrict__ as,
                       const float* __restrict__ ad) {
    int k = threadIdx.x;
    float s = 0.f, d = 0.f;
    for (int j = 0; j < D; j++) {
        float w = W[j * D + k];
        s += as[j] * w;
        d += ad[j] * w;
    }
    g_csrc[k] = s;
    g_cdst[k] = d;
}

// d[t] = delta_dis_embs[t] . c_src
__global__ void k_ddot(const float* __restrict__ dd) {
    int t = blockIdx.x * 128 + threadIdx.x;
    float s = 0.f;
    for (int k = 0; k < D; k++) s += dd[t * D + k] * g_csrc[k];
    g_ddot[t] = s;
}

// per-session start offsets (prefix sum of lengths)
__global__ void k_starts(const int* __restrict__ lens) {
    int b = threadIdx.x;
    int s = 0;
    for (int i = 0; i < b; i++) s += lens[i];
    g_starts[b] = s;
}

// transpose the 6 [128,128] weight matrices: Wt[k][j] = W[j][k]
__global__ void k_trans(const float* __restrict__ in_w, const float* __restrict__ out_w,
                        const float* __restrict__ w1, const float* __restrict__ w2) {
    int m = blockIdx.x >> 6;
    int idx = ((blockIdx.x & 63) << 8) + threadIdx.x; // 0..16383
    int k = idx >> 7, j = idx & 127;
    const float* src;
    if (m < 3) src = in_w + m * D * D;
    else if (m == 3) src = out_w;
    else if (m == 4) src = w1;
    else src = w2;
    g_Wt[m * D * D + k * D + j] = src[j * D + k];
}

// per-vocab-entry attention-logit dots: pv_src[v] = POI[v].c_src etc.
__global__ void k_pv(const float* __restrict__ POI, int V) {
    int v = (blockIdx.x * blockDim.x + threadIdx.x) >> 5;
    int lane = threadIdx.x & 31;
    if (v >= V) return;
    float4 x  = ((const float4*)POI)[(size_t)v * 32 + lane];
    float4 cs = ((const float4*)g_csrc)[lane];
    float4 cd = ((const float4*)g_cdst)[lane];
    float ps = wsum(x.x * cs.x + x.y * cs.y + x.z * cs.z + x.w * cs.w);
    float pd = wsum(x.x * cd.x + x.y * cd.y + x.z * cd.z + x.w * cd.w);
    if (lane == 0) { g_pvs[v] = ps; g_pvd[v] = pd; }
}

// ---------------- fused GCN (2-way softmax over chain neighbors) + LayerNorm1 ----------------
__global__ void k_node(const float* __restrict__ POI, const int* __restrict__ sess,
                       const int* __restrict__ edist, const int* __restrict__ bids,
                       const int* __restrict__ npos, const int* __restrict__ lens,
                       const float* __restrict__ g1, const float* __restrict__ b1v, int N) {
    int n = (blockIdx.x * blockDim.x + threadIdx.x) >> 5;
    int lane = threadIdx.x & 31;
    if (n >= N) return;
    int b = bids[n], p = npos[n], l = lens[b];
    int vi = sess[n];
    bool hasF = (p > 0);
    bool hasB = (p < l - 1);
    float lf = hasF ? (g_pvs[vi] + g_ddot[edist[n - b - 1]]) : -3.0e38f;
    float lb = hasB ? g_pvd[vi] : -3.0e38f;
    float m = fmaxf(lf, lb);
    float ef = hasF ? __expf(lf - m) : 0.f;
    float eb = hasB ? __expf(lb - m) : 0.f;
    float inv = 1.f / (ef + eb + 1e-16f);

    float4 hv = make_float4(0.f, 0.f, 0.f, 0.f);
    if (hasF) {
        float4 xm = ((const float4*)POI)[(size_t)sess[n - 1] * 32 + lane];
        hv.x = ef * xm.x; hv.y = ef * xm.y; hv.z = ef * xm.z; hv.w = ef * xm.w;
    }
    if (hasB) {
        float4 xp = ((const float4*)POI)[(size_t)sess[n + 1] * 32 + lane];
        hv.x += eb * xp.x; hv.y += eb * xp.y; hv.z += eb * xp.z; hv.w += eb * xp.w;
    }
    hv.x *= inv; hv.y *= inv; hv.z *= inv; hv.w *= inv;
    ((float4*)g_H)[(size_t)n * 32 + lane] = hv;

    // LayerNorm1 -> Qn
    float mean = wsum(hv.x + hv.y + hv.z + hv.w) * (1.f / 128.f);
    float4 dx = make_float4(hv.x - mean, hv.y - mean, hv.z - mean, hv.w - mean);
    float var = wsum(dx.x * dx.x + dx.y * dx.y + dx.z * dx.z + dx.w * dx.w) * (1.f / 128.f);
    float r = rsqrtf(var + 1e-8f);
    float4 gg = ((const float4*)g1)[lane];
    float4 bb = ((const float4*)b1v)[lane];
    float4 qn = make_float4(dx.x * r * gg.x + bb.x, dx.y * r * gg.y + bb.y,
                            dx.z * r * gg.z + bb.z, dx.w * r * gg.w + bb.w);
    ((float4*)g_Qn)[(size_t)n * 32 + lane] = qn;
}

// ---------------- tiled fp32 GEMM: C[N,128] = A[N,128] @ W^T (+bias, +res, relu) ----------------
// Wt is pre-transposed: Wt[k][j]. 64-row tile/CTA, 256 threads, 8x4 microtile.
__global__ void __launch_bounds__(256, 2) gemm128_kernel(
    const float* __restrict__ A, const float* __restrict__ Wt,
    const float* __restrict__ bias, const float* __restrict__ res,
    float* __restrict__ C, int N, int relu) {
    extern __shared__ float smem_g[];
    float4* sW = (float4*)smem_g;            // 128 k x 32 float4 (j)
    float*  sA = smem_g + D * D;             // 64 rows x 128 k

    int tid = threadIdx.x;
    const float4* Wt4 = (const float4*)Wt;
#pragma unroll
    for (int i = 0; i < 16; i++) sW[tid + 256 * i] = Wt4[tid + 256 * i];

    int row0 = blockIdx.x * 64;
    int rowsLeft = N - row0;
    const float4* A4 = (const float4*)(A + (size_t)row0 * D);
    float4* sA4 = (float4*)sA;
#pragma unroll
    for (int i = 0; i < 8; i++) {
        int idx = tid + 256 * i;
        float4 val = make_float4(0.f, 0.f, 0.f, 0.f);
        if ((idx >> 5) < rowsLeft) val = A4[idx];
        sA4[idx] = val;
    }
    __syncthreads();

    int ty = tid >> 5;   // row group 0..7
    int tx = tid & 31;   // col group: cols 4*tx..4*tx+3
    float acc[8][4];
#pragma unroll
    for (int r = 0; r < 8; r++)
#pragma unroll
        for (int m = 0; m < 4; m++) acc[r][m] = 0.f;

    const float* sArow = sA + (ty * 8) * D;
#pragma unroll 4
    for (int k = 0; k < D; k++) {
        float4 bf = sW[k * 32 + tx];
#pragma unroll
        for (int r = 0; r < 8; r++) {
            float a = sArow[r * D + k];
            acc[r][0] += a * bf.x;
            acc[r][1] += a * bf.y;
            acc[r][2] += a * bf.z;
            acc[r][3] += a * bf.w;
        }
    }

    float4 bb = ((const float4*)bias)[tx];
#pragma unroll
    for (int r = 0; r < 8; r++) {
        int row = row0 + ty * 8 + r;
        if (row < N) {
            float4 o = make_float4(acc[r][0] + bb.x, acc[r][1] + bb.y,
                                   acc[r][2] + bb.z, acc[r][3] + bb.w);
            if (relu) {
                o.x = fmaxf(o.x, 0.f); o.y = fmaxf(o.y, 0.f);
                o.z = fmaxf(o.z, 0.f); o.w = fmaxf(o.w, 0.f);
            }
            if (res) {
                float4 rv = ((const float4*)res)[(size_t)row * 32 + tx];
                o.x += rv.x; o.y += rv.y; o.z += rv.z; o.w += rv.w;
            }
            ((float4*)C)[(size_t)row * 32 + tx] = o;
        }
    }
}

// ---------------- per-session multi-head attention ----------------
// grid (1024 sessions, 4 heads), 256 threads. K/V staged in padded smem; one warp per q row.
__global__ void __launch_bounds__(256) attn_kernel(const int* __restrict__ lens) {
    __shared__ __align__(16) float sk[MAXLEN * 33];
    __shared__ __align__(16) float sv[MAXLEN * 33];
    __shared__ __align__(16) float ssc[8 * 176];

    int b = blockIdx.x, h = blockIdx.y;
    int l = lens[b];
    int start = g_starts[b];
    int lc = (l + 3) & ~3;
    int tid = threadIdx.x;

    for (int idx = tid; idx < lc * 32; idx += 256) {
        int r = idx >> 5, c = idx & 31;
        float kv = 0.f, vv = 0.f;
        if (r < l) {
            size_t off = (size_t)(start + r) * D + h * 32 + c;
            kv = g_k[off];
            vv = g_v[off];
        }
        sk[r * 33 + c] = kv;
        sv[r * 33 + c] = vv;
    }
    __syncthreads();

    int w = tid >> 5, lane = tid & 31;
    float* myssc = ssc + w * 176;
    const float scale = 0.17677669529663687f; // 1/sqrt(32)

    for (int r = w; r < l; r += 8) {
        float qv = g_q[(size_t)(start + r) * D + h * 32 + lane];
        float qreg[32];
#pragma unroll
        for (int c = 0; c < 32; c++) qreg[c] = __shfl_sync(0xffffffffu, qv, c);

        float sloc[5];
        float mymax = -3.0e38f;
        int nj = 0;
        for (int j = lane; j < l; j += 32) {
            const float* kr = sk + j * 33;
            float dsum = 0.f;
#pragma unroll
            for (int c = 0; c < 32; c++) dsum += qreg[c] * kr[c];
            dsum *= scale;
            sloc[nj++] = dsum;
            mymax = fmaxf(mymax, dsum);
        }
#pragma unroll
        for (int o = 16; o; o >>= 1) mymax = fmaxf(mymax, __shfl_xor_sync(0xffffffffu, mymax, o));

        float mysum = 0.f;
        nj = 0;
        for (int j = lane; j < l; j += 32) {
            float p = __expf(sloc[nj++] - mymax);
            myssc[j] = p;
            mysum += p;
        }
        mysum = wsum(mysum);
        if (lane < 3) {
            int jj = l + lane;
            if (jj < 176) myssc[jj] = 0.f;  // zero-pad to multiple of 4
        }
        __syncwarp();

        float inv = 1.f / mysum;
        float acc = 0.f;
        for (int j = 0; j < lc; j += 4) {
            float4 p4 = *(const float4*)(myssc + j);
            acc += p4.x * sv[(j + 0) * 33 + lane];
            acc += p4.y * sv[(j + 1) * 33 + lane];
            acc += p4.z * sv[(j + 2) * 33 + lane];
            acc += p4.w * sv[(j + 3) * 33 + lane];
        }
        g_ctx[(size_t)(start + r) * D + h * 32 + lane] = acc * inv;
        __syncwarp();
    }
}

// ---------------- LayerNorm2 ----------------
__global__ void k_ln2(const float* __restrict__ g2, const float* __restrict__ b2v, int N) {
    int n = (blockIdx.x * blockDim.x + threadIdx.x) >> 5;
    int lane = threadIdx.x & 31;
    if (n >= N) return;
    float4 x = ((const float4*)g_t1)[(size_t)n * 32 + lane];
    float mean = wsum(x.x + x.y + x.z + x.w) * (1.f / 128.f);
    float4 dx = make_float4(x.x - mean, x.y - mean, x.z - mean, x.w - mean);
    float var = wsum(dx.x * dx.x + dx.y * dx.y + dx.z * dx.z + dx.w * dx.w) * (1.f / 128.f);
    float r = rsqrtf(var + 1e-8f);
    float4 gg = ((const float4*)g2)[lane];
    float4 bb = ((const float4*)b2v)[lane];
    float4 o = make_float4(dx.x * r * gg.x + bb.x, dx.y * r * gg.y + bb.y,
                           dx.z * r * gg.z + bb.z, dx.w * r * gg.w + bb.w);
    ((float4*)g_o2)[(size_t)n * 32 + lane] = o;
}

// ---------------- masked mean pool ----------------
__global__ void k_pool(const int* __restrict__ lens, float* __restrict__ out) {
    int b = (blockIdx.x * blockDim.x + threadIdx.x) >> 5;
    int lane = threadIdx.x & 31;
    if (b >= BATCH) return;
    int l = lens[b], s = g_starts[b];
    float4 acc = make_float4(0.f, 0.f, 0.f, 0.f);
    for (int p = 0; p < l; p++) {
        float4 v = ((const float4*)g_fin)[(size_t)(s + p) * 32 + lane];
        acc.x += v.x; acc.y += v.y; acc.z += v.z; acc.w += v.w;
    }
    float iv = 1.f / (float)l;
    float4 o = make_float4(acc.x * iv, acc.y * iv, acc.z * iv, acc.w * iv);
    ((float4*)out)[b * 32 + lane] = o;
}

// ---------------- launch ----------------
extern "C" void kernel_launch(void* const* d_in, const int* in_sizes, int n_in,
                              void* d_out, int out_size) {
    const float* POI   = (const float*)d_in[0];
    const float* ddis  = (const float*)d_in[1];
    const float* attW  = (const float*)d_in[2];
    const float* a_src = (const float*)d_in[3];
    const float* a_dst = (const float*)d_in[4];
    const float* in_w  = (const float*)d_in[5];
    const float* in_b  = (const float*)d_in[6];
    const float* out_w = (const float*)d_in[7];
    const float* out_b = (const float*)d_in[8];
    const float* ln1g  = (const float*)d_in[9];
    const float* ln1b  = (const float*)d_in[10];
    const float* ln2g  = (const float*)d_in[11];
    const float* ln2b  = (const float*)d_in[12];
    const float* w1    = (const float*)d_in[13];
    const float* b1    = (const float*)d_in[14];
    const float* w2    = (const float*)d_in[15];
    const float* b2    = (const float*)d_in[16];
    const int* sess  = (const int*)d_in[17];
    const int* edist = (const int*)d_in[18];
    const int* bids  = (const int*)d_in[20];
    const int* npos  = (const int*)d_in[21];
    const int* lens  = (const int*)d_in[22];
    int N = in_sizes[17];
    int V = in_sizes[0] / D;

    float *pH, *pQn, *pq, *pk, *pv, *pctx, *pt1, *po2, *pf1, *pfin, *pWt;
    cudaGetSymbolAddress((void**)&pH, g_H);
    cudaGetSymbolAddress((void**)&pQn, g_Qn);
    cudaGetSymbolAddress((void**)&pq, g_q);
    cudaGetSymbolAddress((void**)&pk, g_k);
    cudaGetSymbolAddress((void**)&pv, g_v);
    cudaGetSymbolAddress((void**)&pctx, g_ctx);
    cudaGetSymbolAddress((void**)&pt1, g_t1);
    cudaGetSymbolAddress((void**)&po2, g_o2);
    cudaGetSymbolAddress((void**)&pf1, g_f1);
    cudaGetSymbolAddress((void**)&pfin, g_fin);
    cudaGetSymbolAddress((void**)&pWt, g_Wt);

    size_t gsh = (size_t)(D * D + 64 * D) * sizeof(float); // 96 KB
    cudaFuncSetAttribute(gemm128_kernel, cudaFuncAttributeMaxDynamicSharedMemorySize, (int)gsh);

    k_cvec<<<1, 128>>>(attW, a_src, a_dst);
    k_ddot<<<4, 128>>>(ddis);
    k_starts<<<1, 1024>>>(lens);
    k_trans<<<6 * 64, 256>>>(in_w, out_w, w1, w2);
    k_pv<<<(V + 7) / 8, 256>>>(POI, V);
    k_node<<<(N + 7) / 8, 256>>>(POI, sess, edist, bids, npos, lens, ln1g, ln1b, N);

    int gb = (N + 63) / 64;
    // Q/K/V projections
    gemm128_kernel<<<gb, 256, gsh>>>(pQn, pWt + 0 * D * D, in_b,       nullptr, pq, N, 0);
    gemm128_kernel<<<gb, 256, gsh>>>(pH,  pWt + 1 * D * D, in_b + D,   nullptr, pk, N, 0);
    gemm128_kernel<<<gb, 256, gsh>>>(pH,  pWt + 2 * D * D, in_b + 2*D, nullptr, pv, N, 0);
    // attention
    attn_kernel<<<dim3(BATCH, 4), 256>>>(lens);
    // out_proj + residual(Qn), then LN2
    gemm128_kernel<<<gb, 256, gsh>>>(pctx, pWt + 3 * D * D, out_b, pQn, pt1, N, 0);
    k_ln2<<<(N + 7) / 8, 256>>>(ln2g, ln2b, N);
    // FFN with residual
    gemm128_kernel<<<gb, 256, gsh>>>(po2, pWt + 4 * D * D, b1, nullptr, pf1, N, 1);
    gemm128_kernel<<<gb, 256, gsh>>>(pf1, pWt + 5 * D * D, b2, po2,    pfin, N, 0);
    // masked mean pool
    k_pool<<<(BATCH + 7) / 8, 256>>>(lens, (float*)d_out);
}